// round 11
// baseline (speedup 1.0000x reference)
#include <cuda_runtime.h>
#include <cuda_bf16.h>
#include <cstdint>

#define NT 128
#define VB 32
#define TS 24
#define GRID 512

// weights in bf16 B-frag layout (prep kernel output)
__device__ uint32_t g_whF[4 * 6144];
__device__ uint32_t g_wiF[3 * 6144];
// layers 0-2 activations as bf16 A-frag tiles: [t][blk][256 x uint4] = 50 MB
__device__ uint4 g_actb[TS * GRID * 256];
// layer-3 output fp32, head layout [t][j][v_global] = 100 MB
__device__ float g_act2[TS * 64 * 16384];

// ---- smem float offsets (16 KB total) ----
#define S_H0  0      // 1024 fl: h A-frags buf0 (256 uint4)
#define S_H1  1024
#define S_BS  2048   // 4 x 256 fused biases
#define S_W0  3072   // 192 layer-0 rank-1 ih weights
#define S_VIN 3264   // 768 vin[t][v]
#define SMEM_FLOATS 4096   // 16,384 B; head reuses [0,4096) as A/B ping-pong

static __device__ __forceinline__ uint32_t pkbf(float lo, float hi) {
    __nv_bfloat162 b = __float22bfloat162_rn(make_float2(lo, hi));
    return *(uint32_t*)&b;
}
static __device__ __forceinline__ float tanha(float x) {
    float y; asm("tanh.approx.f32 %0, %1;" : "=f"(y) : "f"(x)); return y;
}
static __device__ __forceinline__ float sigt(float x) {
    return fmaf(tanha(0.5f * x), 0.5f, 0.5f);
}
#define MMAB(c, a, b) asm volatile( \
    "mma.sync.aligned.m16n8k16.row.col.f32.bf16.bf16.f32 " \
    "{%0,%1,%2,%3},{%4,%5,%6,%7},{%8,%9},{%0,%1,%2,%3};" \
    : "+f"((c)[0]), "+f"((c)[1]), "+f"((c)[2]), "+f"((c)[3]) \
    : "r"((a).x), "r"((a).y), "r"((a).z), "r"((a).w), "r"((b).x), "r"((b).y))

// ---- prep: convert GRU weights to bf16 B-frag global arrays ----
__global__ void __launch_bounds__(512)
prep_kernel(const float* __restrict__ wih0, const float* __restrict__ whh0,
            const float* __restrict__ wihL, const float* __restrict__ whhL)
{
    int idx = blockIdx.x * 512 + threadIdx.x;
    if (idx >= 43008) return;
    const float* W;
    uint32_t* dst;
    int i;
    if (idx < 24576) {
        int l = idx / 6144; i = idx % 6144;
        W = (l == 0) ? whh0 : whhL + (l - 1) * 12288;
        dst = g_whF + l * 6144 + i;
    } else {
        int r = idx - 24576;
        int l = r / 6144; i = r % 6144;
        W = wihL + l * 12288;
        dst = g_wiF + l * 6144 + i;
    }
    int gt = i >> 8, kt2 = (i >> 6) & 3, ln = (i >> 1) & 31, br = i & 1;
    int g = gt * 8 + (ln >> 2);
    int k = kt2 * 16 + (ln & 3) * 2 + br * 8;
    *dst = pkbf(W[g * 64 + k], W[g * 64 + k + 1]);
}

// One GRU layer, 24 steps, one chain per block (4 warps, one per SMSP).
// Warp w = ng (j 16w..16w+15); every warp covers both 16-voxel halves (mt=0,1).
template<bool L0, bool LAST>
static __device__ void layer_run(float* __restrict__ sm, int tid, int blk,
                                 const uint2* __restrict__ WHu,
                                 const uint2* __restrict__ WIu,
                                 const float* __restrict__ BS)
{
    const int lane = tid & 31, ng = tid >> 5;
    const int gq = lane >> 2, cc = lane & 3;
    float hp[16];
    #pragma unroll
    for (int i = 0; i < 16; ++i) hp[i] = 0.f;

    for (int t = 0; t < TS; ++t) {
        uint4*       hb_n = (uint4*)(sm + ((t & 1) ? S_H0 : S_H1));
        const uint4* hb_c = (const uint4*)(sm + ((t & 1) ? S_H1 : S_H0));

        float cr[4][4], cz[4][4], cnh[4][4], cnx[4][4];
        #pragma unroll
        for (int f = 0; f < 4; ++f)
            #pragma unroll
            for (int q = 0; q < 4; ++q) {
                cr[f][q] = 0.f; cz[f][q] = 0.f; cnh[f][q] = 0.f; cnx[f][q] = 0.f;
            }

        // ---- pass 1: ih MMAs; x streamed from global (evict-first) ----
        if (!L0) {
            const uint4* xs = &g_actb[(size_t)(t * GRID + blk) * 256];
            #pragma unroll
            for (int kt2 = 0; kt2 < 4; ++kt2) {
                uint2 bi2[6];
                #pragma unroll
                for (int ji = 0; ji < 2; ++ji) {
                    int jt = 2 * ng + ji;
                    bi2[ji*3+0] = WIu[((jt)      * 4 + kt2) * 32 + lane];
                    bi2[ji*3+1] = WIu[((8 + jt)  * 4 + kt2) * 32 + lane];
                    bi2[ji*3+2] = WIu[((16 + jt) * 4 + kt2) * 32 + lane];
                }
                #pragma unroll
                for (int mi = 0; mi < 2; ++mi) {
                    uint4 ax = __ldcs(&xs[(mi * 4 + kt2) * 32 + lane]);
                    #pragma unroll
                    for (int ji = 0; ji < 2; ++ji) {
                        int f = mi * 2 + ji;
                        MMAB(cr[f],  ax, bi2[ji*3+0]);
                        MMAB(cz[f],  ax, bi2[ji*3+1]);
                        MMAB(cnx[f], ax, bi2[ji*3+2]);
                    }
                }
            }
        }

        // ---- pass 2: hh MMAs (h frags from smem; skipped at t=0) ----
        if (t > 0) {
            #pragma unroll
            for (int kt2 = 0; kt2 < 4; ++kt2) {
                uint2 bh[6];
                #pragma unroll
                for (int ji = 0; ji < 2; ++ji) {
                    int jt = 2 * ng + ji;
                    bh[ji*3+0] = WHu[((jt)      * 4 + kt2) * 32 + lane];
                    bh[ji*3+1] = WHu[((8 + jt)  * 4 + kt2) * 32 + lane];
                    bh[ji*3+2] = WHu[((16 + jt) * 4 + kt2) * 32 + lane];
                }
                #pragma unroll
                for (int mi = 0; mi < 2; ++mi) {
                    uint4 ah = hb_c[(mi * 4 + kt2) * 32 + lane];
                    #pragma unroll
                    for (int ji = 0; ji < 2; ++ji) {
                        int f = mi * 2 + ji;
                        MMAB(cr[f],  ah, bh[ji*3+0]);
                        MMAB(cz[f],  ah, bh[ji*3+1]);
                        MMAB(cnh[f], ah, bh[ji*3+2]);
                    }
                }
            }
        }

        // ---- thread-local combine; h packs straight into A-frag uint4 ----
        #pragma unroll
        for (int mi = 0; mi < 2; ++mi) {
            uint32_t rg[4];
            #pragma unroll
            for (int ji = 0; ji < 2; ++ji) {
                int f = mi * 2 + ji;
                float hv[4];
                #pragma unroll
                for (int q = 0; q < 4; ++q) {
                    int j = 16 * ng + 8 * ji + 2 * cc + (q & 1);
                    int v = mi * 16 + gq + 8 * (q >> 1);
                    float xr = 0.f, xz = 0.f, xn;
                    if (L0) {
                        float xv = sm[S_VIN + t * VB + v];
                        xr = xv * sm[S_W0 + j];
                        xz = xv * sm[S_W0 + 64 + j];
                        xn = xv * sm[S_W0 + 128 + j] + BS[192 + j];
                    } else {
                        xn = cnx[f][q] + BS[192 + j];
                    }
                    float r  = sigt(cr[f][q] + xr + BS[j]);
                    float z  = sigt(cz[f][q] + xz + BS[64 + j]);
                    float nn = tanha(xn + r * (cnh[f][q] + BS[128 + j]));
                    float hnv = (1.f - z) * nn + z * hp[f * 4 + q];
                    hp[f * 4 + q] = hnv;
                    hv[q] = hnv;
                    if (LAST)
                        __stcs(&g_act2[((size_t)(t * 64 + j) << 14) + blk * VB + v], hnv);
                }
                rg[ji * 2 + 0] = pkbf(hv[0], hv[1]);
                rg[ji * 2 + 1] = pkbf(hv[2], hv[3]);
            }
            uint4 u = make_uint4(rg[0], rg[1], rg[2], rg[3]);
            hb_n[(mi * 4 + ng) * 32 + lane] = u;
            if (!LAST)
                __stcs(&g_actb[(size_t)(t * GRID + blk) * 256 + (mi * 4 + ng) * 32 + lane], u);
        }
        __syncthreads();
    }
}

__global__ void __launch_bounds__(NT, 4)
fused_rnn_kernel(const float* __restrict__ x,   const int*   __restrict__ lengths,
                 const float* __restrict__ sf,  const float* __restrict__ bp,
                 const float* __restrict__ wih0,const float* __restrict__ whh0,
                 const float* __restrict__ bih0,const float* __restrict__ bhh0,
                 const float* __restrict__ wihL,const float* __restrict__ whhL,
                 const float* __restrict__ bihL,const float* __restrict__ bhhL,
                 const float* __restrict__ bng, const float* __restrict__ bnb,
                 const float* __restrict__ bnm, const float* __restrict__ bnv,
                 const float* __restrict__ fcW, const float* __restrict__ fcb,
                 const float* __restrict__ fcWo,const float* __restrict__ fcbo,
                 float* __restrict__ out)
{
    extern __shared__ float sm[];
    const int tid = threadIdx.x;
    const int blk = blockIdx.x;
    const int vbase = blk * VB;
    const int n  = vbase >> 12;
    const int sb = vbase & 4095;

    // stage fused biases (all 4 layers), layer-0 rank-1 weights, vin
    for (int l = 0; l < 4; ++l) {
        const float* Bi = (l == 0) ? bih0 : bihL + (l - 1) * 192;
        const float* Bh = (l == 0) ? bhh0 : bhhL + (l - 1) * 192;
        if (tid < 64) {
            int j = tid;
            sm[S_BS + l * 256 + j]       = Bi[j] + Bh[j];
            sm[S_BS + l * 256 + 64 + j]  = Bi[64 + j] + Bh[64 + j];
            sm[S_BS + l * 256 + 128 + j] = Bh[128 + j];
            sm[S_BS + l * 256 + 192 + j] = Bi[128 + j];
        }
    }
    if (tid < 192) sm[S_W0 + tid] = wih0[tid];
    for (int idx = tid; idx < TS * VB; idx += NT) {   // vin[t][v]
        int t = idx >> 5, v = idx & 31;
        int p = t % 3;
        sm[S_VIN + idx] = x[n * 98304 + t * 4096 + sb + v] * sf[p] + bp[p];
    }
    __syncthreads();

    layer_run<true , false>(sm, tid, blk, (const uint2*)g_whF,
                            (const uint2*)g_wiF, sm + S_BS);
    layer_run<false, false>(sm, tid, blk, (const uint2*)(g_whF + 6144),
                            (const uint2*)g_wiF, sm + S_BS + 256);
    layer_run<false, false>(sm, tid, blk, (const uint2*)(g_whF + 12288),
                            (const uint2*)(g_wiF + 6144), sm + S_BS + 512);
    layer_run<false, true >(sm, tid, blk, (const uint2*)(g_whF + 18432),
                            (const uint2*)(g_wiF + 12288), sm + S_BS + 768);
    __syncthreads();

    // ---- head: sel = h[len-1]+h[len-4]; 5x (BN+SiLU+FC); BN+SiLU; out ----
    float* A = sm;          // [j][v] 64 x 32
    float* B = sm + 2048;
    const int len = lengths[n];
    const int t1 = len - 1, t2 = len - 4;
    #pragma unroll
    for (int it = 0; it < 16; ++it) {
        int idx = tid + it * NT, v = idx & 31, j = idx >> 5;
        A[j * VB + v] = g_act2[((size_t)(t1 * 64 + j) << 14) + vbase + v]
                      + g_act2[((size_t)(t2 * 64 + j) << 14) + vbase + v];
    }
    __syncthreads();
    for (int i = 0; i < 5; ++i) {
        #pragma unroll
        for (int it = 0; it < 16; ++it) {
            int idx = tid + it * NT, v = idx & 31, j = idx >> 5;
            float y = bng[i * 64 + j] * (A[j * VB + v] - bnm[i * 64 + j])
                      * rsqrtf(bnv[i * 64 + j] + 1e-5f) + bnb[i * 64 + j];
            A[j * VB + v] = y * sigt(y);
        }
        __syncthreads();
        const float* Wl = fcW + i * 4096;
        #pragma unroll
        for (int it = 0; it < 16; ++it) {
            int idx = tid + it * NT, v = idx & 31, o = idx >> 5;
            float acc = fcb[i * 64 + o];
            #pragma unroll 8
            for (int j = 0; j < 64; ++j) acc += A[j * VB + v] * Wl[o * 64 + j];
            B[o * VB + v] = acc;
        }
        __syncthreads();
        float* tswp = A; A = B; B = tswp;
    }
    #pragma unroll
    for (int it = 0; it < 16; ++it) {
        int idx = tid + it * NT, v = idx & 31, j = idx >> 5;
        float y = bng[5 * 64 + j] * (A[j * VB + v] - bnm[5 * 64 + j])
                  * rsqrtf(bnv[5 * 64 + j] + 1e-5f) + bnb[5 * 64 + j];
        A[j * VB + v] = y * sigt(y);
    }
    __syncthreads();
    if (tid < VB) {
        float acc = fcbo[0];
        #pragma unroll 8
        for (int j = 0; j < 64; ++j) acc += A[j * VB + tid] * fcWo[j];
        out[vbase + tid] = acc;
    }
}

extern "C" void kernel_launch(void* const* d_in, const int* in_sizes, int n_in,
                              void* d_out, int out_size)
{
    const float* x     = (const float*)d_in[0];
    const int*   lens  = (const int*)  d_in[1];
    const float* sf    = (const float*)d_in[2];
    const float* bp    = (const float*)d_in[3];
    const float* wih0  = (const float*)d_in[4];
    const float* whh0  = (const float*)d_in[5];
    const float* bih0  = (const float*)d_in[6];
    const float* bhh0  = (const float*)d_in[7];
    const float* wihL  = (const float*)d_in[8];
    const float* whhL  = (const float*)d_in[9];
    const float* bihL  = (const float*)d_in[10];
    const float* bhhL  = (const float*)d_in[11];
    const float* bng   = (const float*)d_in[12];
    const float* bnb   = (const float*)d_in[13];
    const float* bnm   = (const float*)d_in[14];
    const float* bnv   = (const float*)d_in[15];
    const float* fcW   = (const float*)d_in[16];
    const float* fcb   = (const float*)d_in[17];
    const float* fcWo  = (const float*)d_in[18];
    const float* fcbo  = (const float*)d_in[19];
    float* out = (float*)d_out;

    prep_kernel<<<84, 512>>>(wih0, whh0, wihL, whhL);

    const size_t smem = SMEM_FLOATS * sizeof(float);   // 16,384 B
    cudaFuncSetAttribute(fused_rnn_kernel,
                         cudaFuncAttributeMaxDynamicSharedMemorySize, (int)smem);
    fused_rnn_kernel<<<GRID, NT, smem>>>(
        x, lens, sf, bp, wih0, whh0, bih0, bhh0,
        wihL, whhL, bihL, bhhL, bng, bnb, bnm, bnv,
        fcW, fcb, fcWo, fcbo, out);
}